// round 15
// baseline (speedup 1.0000x reference)
#include <cuda_runtime.h>
#include <cuda_bf16.h>
#include <cstdint>

// FineMatching (P=512, R=S=128, K=3, THRESH=0.05, OR-combine, conditional).
// R15: software-pipelined 2 proposals per 2-CTA cluster.
//   Grid 512 CTAs x 256 thr; cluster q owns proposals 2q,2q+1; rank h owns
//   rows [64h,64h+64) of both. Both tiles' cp.async fills issued up front
//   (2 commit groups); item1's load latency hides under item0's
//   scan/exchange/output. DSMEM col-partial exchange per item; raw-x
//   thresholds; __stcs stores. Dynamic smem ~74KB -> 3 CTAs/SM.

#define PP 512
#define NT 256
#define XTHRESH (-2.99573227355f)   // ln(0.05)

// dynamic smem layout (float offsets)
#define TILE0_F   0          // 64*132 = 8448
#define TILE1_F   8448
#define CPA_F     16896      // item0 cp1|cp2|cp3, 3*128
#define CPB_F     17280      // item1 cp1|cp2|cp3
#define COLT0_F   17664      // 128
#define COLT1_F   17792
#define SMF0_F    17920      // 128
#define SMF1_F    18048
#define RINF0_F   18176      // float2[64]
#define RINF1_F   18304
#define NCS_F     18432      // 2
#define SMEM_F    18440      // 73760 bytes

struct Top3 { float v1, v2, v3; };

__device__ __forceinline__ void ins3(Top3& t, float v) {
    float t1 = fminf(t.v1, v);
    float t2 = fminf(t.v2, v);
    t.v1 = fmaxf(t.v1, v);
    t.v2 = fmaxf(t.v2, t1);
    t.v3 = fmaxf(t.v3, t2);
}

__device__ __forceinline__ void merge(Top3& a, const Top3& b) {
    ins3(a, b.v1);
    ins3(a, b.v2);
    ins3(a, b.v3);
}

__device__ __forceinline__ void merge_xor1(Top3& t) {
    Top3 b;
    b.v1 = __shfl_xor_sync(0xffffffffu, t.v1, 1);
    b.v2 = __shfl_xor_sync(0xffffffffu, t.v2, 1);
    b.v3 = __shfl_xor_sync(0xffffffffu, t.v3, 1);
    merge(t, b);
}

#define T3INIT {-1e30f, -1e30f, -1e30f}

__device__ __forceinline__ float ld_peer_f32(uint32_t local_saddr, uint32_t peer_rank) {
    uint32_t ra;
    float v;
    asm volatile("mapa.shared::cluster.u32 %0, %1, %2;"
                 : "=r"(ra) : "r"(local_saddr), "r"(peer_rank));
    asm volatile("ld.shared::cluster.f32 %0, [%1];" : "=f"(v) : "r"(ra));
    return v;
}

// P2: local scans over one 64x132 tile (cols by thr 0..127, rows by 128..255)
__device__ __forceinline__ void scan_item(const float* tile, float* cp,
                                          float2* rowInfo, int tid) {
    if (tid < 128) {
        const float* base = tile + tid;
        Top3 t0 = T3INIT, t1 = T3INIT, t2 = T3INIT, t3 = T3INIT;
        #pragma unroll
        for (int j = 0; j < 16; j++) {
            ins3(t0, base[(4 * j + 0) * 132]);
            ins3(t1, base[(4 * j + 1) * 132]);
            ins3(t2, base[(4 * j + 2) * 132]);
            ins3(t3, base[(4 * j + 3) * 132]);
        }
        merge(t0, t1);
        merge(t2, t3);
        merge(t0, t2);
        cp[tid]       = t0.v1;
        cp[128 + tid] = t0.v2;
        cp[256 + tid] = t0.v3;
    } else {
        const int u  = tid - 128;
        const int r  = u >> 1;
        const int hf = u & 1;
        Top3 t0 = T3INIT, t1 = T3INIT, t2 = T3INIT, t3 = T3INIT;
        const float4* ra = (const float4*)tile + r * 33 + (hf ? 20 : 0);
        #pragma unroll
        for (int j = 0; j < 12; j++) {
            float4 v = ra[j];
            ins3(t0, v.x);
            ins3(t1, v.y);
            ins3(t2, v.z);
            ins3(t3, v.w);
        }
        const float4* rb = (const float4*)tile + r * 33 + (hf ? 16 : 12);
        #pragma unroll
        for (int j = 0; j < 4; j++) {
            float4 v = rb[j];
            ins3(t0, v.x);
            ins3(t1, v.y);
            ins3(t2, v.z);
            ins3(t3, v.w);
        }
        merge(t0, t1);
        merge(t2, t3);
        merge(t0, t2);
        merge_xor1(t0);
        if (!hf) rowInfo[r].x = t0.v3;
    }
}

// merge own + peer col partials -> colT (threads 0..127)
__device__ __forceinline__ void merge_cols(float* cp, float* colT,
                                           uint32_t peer, int tid) {
    if (tid < 128) {
        Top3 t;
        t.v1 = cp[tid];
        t.v2 = cp[128 + tid];
        t.v3 = cp[256 + tid];
        uint32_t a = (uint32_t)__cvta_generic_to_shared(cp + tid);
        ins3(t, ld_peer_f32(a, peer));
        ins3(t, ld_peer_f32(a + 128 * 4, peer));
        ins3(t, ld_peer_f32(a + 256 * 4, peer));
        colT[tid] = t.v3;
    }
}

__device__ __forceinline__ void output_item(
    const float* tile, const float2* rowInfo, const float* colT,
    const float* smF, float scale, float4* sco, float4* cor,
    int write_corr, int tid, int lane)
{
    const float4 cT = *(const float4*)(colT + 4 * lane);
    const float4 m4 = *(const float4*)(smF + 4 * lane);
    const float4* tp  = (const float4*)tile + (tid >> 5) * 33 + lane;
    const float2* rip = rowInfo + (tid >> 5);

    if (write_corr) {
        #pragma unroll
        for (int k = 0; k < 8; k++) {
            float2 ri = rip[8 * k];
            float4 x  = tp[k * 8 * 33];

            bool ax = x.x >= ri.x, bx = x.x >= cT.x;
            bool ay = x.y >= ri.x, by = x.y >= cT.y;
            bool az = x.z >= ri.x, bz = x.z >= cT.z;
            bool aw = x.w >= ri.x, bw = x.w >= cT.w;

            float svx = scale * __expf(x.x), svy = scale * __expf(x.y);
            float svz = scale * __expf(x.z), svw = scale * __expf(x.w);

            float4 s4;
            s4.x = (ax ? svx : 0.f) + (bx ? svx : 0.f);
            s4.y = (ay ? svy : 0.f) + (by ? svy : 0.f);
            s4.z = (az ? svz : 0.f) + (bz ? svz : 0.f);
            s4.w = (aw ? svw : 0.f) + (bw ? svw : 0.f);
            __stcs(sco + k * NT, s4);

            float4 c4;
            c4.x = ((ax || bx) && x.x > XTHRESH) ? ri.y * m4.x : 0.f;
            c4.y = ((ay || by) && x.y > XTHRESH) ? ri.y * m4.y : 0.f;
            c4.z = ((az || bz) && x.z > XTHRESH) ? ri.y * m4.z : 0.f;
            c4.w = ((aw || bw) && x.w > XTHRESH) ? ri.y * m4.w : 0.f;
            __stcs(cor + k * NT, c4);
        }
    } else {
        #pragma unroll
        for (int k = 0; k < 8; k++) {
            float2 ri = rip[8 * k];
            float4 x  = tp[k * 8 * 33];
            bool ax = x.x >= ri.x, bx = x.x >= cT.x;
            bool ay = x.y >= ri.x, by = x.y >= cT.y;
            bool az = x.z >= ri.x, bz = x.z >= cT.z;
            bool aw = x.w >= ri.x, bw = x.w >= cT.w;
            float svx = scale * __expf(x.x), svy = scale * __expf(x.y);
            float svz = scale * __expf(x.z), svw = scale * __expf(x.w);
            float4 s4;
            s4.x = (ax ? svx : 0.f) + (bx ? svx : 0.f);
            s4.y = (ay ? svy : 0.f) + (by ? svy : 0.f);
            s4.z = (az ? svz : 0.f) + (bz ? svz : 0.f);
            s4.w = (aw ? svw : 0.f) + (bw ? svw : 0.f);
            __stcs(sco + k * NT, s4);
        }
    }
}

__global__ __launch_bounds__(NT, 3) __cluster_dims__(2, 1, 1)
void fine_matching_kernel(
    const float4* __restrict__ msm4,        // [P,R,S] as float4 (raw log-scores)
    const unsigned int* __restrict__ refm,  // [P,R] 32-bit bool
    const unsigned int* __restrict__ srcm,  // [P,S] 32-bit bool
    const float* __restrict__ ncs,          // [P]
    float4* __restrict__ out4,              // [score | corr] as float4
    int write_corr)
{
    extern __shared__ __align__(16) float sh[];
    float*  tile0 = sh + TILE0_F;
    float*  tile1 = sh + TILE1_F;
    float*  cpA   = sh + CPA_F;
    float*  cpB   = sh + CPB_F;
    float*  colT0 = sh + COLT0_F;
    float*  colT1 = sh + COLT1_F;
    float*  smF0  = sh + SMF0_F;
    float*  smF1  = sh + SMF1_F;
    float2* rInf0 = (float2*)(sh + RINF0_F);
    float2* rInf1 = (float2*)(sh + RINF1_F);
    float*  ncsS  = sh + NCS_F;

    const int bid  = blockIdx.x;
    const int q    = bid >> 1;               // cluster index
    const int half = bid & 1;                // == cluster rank
    const int p0   = 2 * q;
    const int p1   = 2 * q + 1;
    const uint32_t peer = (uint32_t)(half ^ 1);
    const int tid  = threadIdx.x;
    const int lane = tid & 31;

    // ---- P0a: prefetch both items' scalars (overlap with fills)
    float pf0 = 0.0f, pf1 = 0.0f;
    if (tid < 64) {
        pf0 = (refm[p0 * 128 + half * 64 + tid] != 0u) ? 1.0f : 0.0f;
        pf1 = (refm[p1 * 128 + half * 64 + tid] != 0u) ? 1.0f : 0.0f;
    } else if (tid < 192) {
        pf0 = (srcm[p0 * 128 + (tid - 64)] != 0u) ? 1.0f : 0.0f;
        pf1 = (srcm[p1 * 128 + (tid - 64)] != 0u) ? 1.0f : 0.0f;
    } else if (tid == 192) {
        pf0 = 0.5f * ncs[p0];
        pf1 = 0.5f * ncs[p1];
    }

    // ---- P1: issue BOTH tile fills (2 commit groups, 16 x 16B in flight)
    {
        const float4* g0 = msm4 + p0 * 4096 + half * 2048 + tid;
        const float4* g1 = msm4 + p1 * 4096 + half * 2048 + tid;
        uint32_t s0 = (uint32_t)__cvta_generic_to_shared(
            (float4*)tile0 + (tid >> 5) * 33 + lane);
        uint32_t s1 = (uint32_t)__cvta_generic_to_shared(
            (float4*)tile1 + (tid >> 5) * 33 + lane);
        #pragma unroll
        for (int k = 0; k < 8; k++)
            asm volatile("cp.async.cg.shared.global [%0], [%1], 16;"
                         :: "r"(s0 + k * (8 * 33 * 16)), "l"(g0 + k * NT));
        asm volatile("cp.async.commit_group;");
        #pragma unroll
        for (int k = 0; k < 8; k++)
            asm volatile("cp.async.cg.shared.global [%0], [%1], 16;"
                         :: "r"(s1 + k * (8 * 33 * 16)), "l"(g1 + k * NT));
        asm volatile("cp.async.commit_group;");
    }

    // ---- P0b: park scalars
    if (tid < 64) {
        rInf0[tid].y = pf0;
        rInf1[tid].y = pf1;
    } else if (tid < 192) {
        smF0[tid - 64] = pf0;
        smF1[tid - 64] = pf1;
    } else if (tid == 192) {
        ncsS[0] = pf0;
        ncsS[1] = pf1;
    }

    // ================= ITEM 0 (tile1's load hides under all of this) ======
    asm volatile("cp.async.wait_group 1;" ::: "memory");
    __syncthreads();

    scan_item(tile0, cpA, rInf0, tid);
    __syncthreads();

    asm volatile("barrier.cluster.arrive.aligned;" ::: "memory");
    asm volatile("barrier.cluster.wait.aligned;" ::: "memory");
    merge_cols(cpA, colT0, peer, tid);
    __syncthreads();

    {
        float4* sco = out4 + (size_t)p0 * 4096 + half * 2048 + tid;
        float4* cor = sco + (size_t)PP * 4096;
        output_item(tile0, rInf0, colT0, smF0, ncsS[0], sco, cor,
                    write_corr, tid, lane);
    }

    // ================= ITEM 1 =============================================
    asm volatile("cp.async.wait_group 0;" ::: "memory");
    __syncthreads();

    scan_item(tile1, cpB, rInf1, tid);
    __syncthreads();

    asm volatile("barrier.cluster.arrive.aligned;" ::: "memory");
    asm volatile("barrier.cluster.wait.aligned;" ::: "memory");
    merge_cols(cpB, colT1, peer, tid);
    __syncthreads();
    // last touch of peer smem was above; arrive final barrier early
    asm volatile("barrier.cluster.arrive.aligned;" ::: "memory");

    {
        float4* sco = out4 + (size_t)p1 * 4096 + half * 2048 + tid;
        float4* cor = sco + (size_t)PP * 4096;
        output_item(tile1, rInf1, colT1, smF1, ncsS[1], sco, cor,
                    write_corr, tid, lane);
    }

    // don't exit while peer may still read my cpB
    asm volatile("barrier.cluster.wait.aligned;" ::: "memory");
}

extern "C" void kernel_launch(void* const* d_in, const int* in_sizes, int n_in,
                              void* d_out, int out_size) {
    const float4* msm4       = (const float4*)d_in[0];
    const unsigned int* refm = (const unsigned int*)d_in[1];
    const unsigned int* srcm = (const unsigned int*)d_in[2];
    const float* ncs         = (const float*)d_in[3];
    float4* out4             = (float4*)d_out;

    const int prs = PP * 128 * 128;
    int write_corr = (out_size >= 2 * prs) ? 1 : 0;

    size_t smem = (size_t)SMEM_F * sizeof(float);   // ~73.8KB
    cudaFuncSetAttribute(fine_matching_kernel,
                         cudaFuncAttributeMaxDynamicSharedMemorySize, (int)smem);

    fine_matching_kernel<<<PP, NT, smem>>>(msm4, refm, srcm, ncs, out4,
                                           write_corr);
}

// round 16
// speedup vs baseline: 1.1485x; 1.1485x over previous
#include <cuda_runtime.h>
#include <cuda_bf16.h>
#include <cstdint>

// FineMatching (P=512, R=S=128, K=3, THRESH=0.05, OR-combine, conditional).
// FINAL = R9 (best measured: 19.0us bench / ~20.5us ncu). 2-CTA clusters,
// one half-proposal (64 rows x 128 cols) per CTA:
//   grid 1024 x 256 thr, ~36KB smem -> 6 CTAs/SM; tail granule halved.
//   Rows: local top-3. Cols: 64-row partial top-3, exchanged with cluster
//   peer via DSMEM (mapa + ld.shared::cluster), merged locally.
//   Thresholds on raw x (exp monotone); score uses __expf; __stcs stores.
// All alternatives measured and slower across R4-R15 (occupancy, MLP,
// ALU cuts, TMA stores, splits, shadow fusion, 2-item pipelining).

#define PP 512
#define NT 256
#define XTHRESH (-2.99573227355f)   // ln(0.05)

struct Top3 { float v1, v2, v3; };

__device__ __forceinline__ void ins3(Top3& t, float v) {
    float t1 = fminf(t.v1, v);
    float t2 = fminf(t.v2, v);
    t.v1 = fmaxf(t.v1, v);
    t.v2 = fmaxf(t.v2, t1);
    t.v3 = fmaxf(t.v3, t2);
}

__device__ __forceinline__ void merge(Top3& a, const Top3& b) {
    ins3(a, b.v1);
    ins3(a, b.v2);
    ins3(a, b.v3);
}

__device__ __forceinline__ void merge_xor1(Top3& t) {
    Top3 b;
    b.v1 = __shfl_xor_sync(0xffffffffu, t.v1, 1);
    b.v2 = __shfl_xor_sync(0xffffffffu, t.v2, 1);
    b.v3 = __shfl_xor_sync(0xffffffffu, t.v3, 1);
    merge(t, b);
}

#define T3INIT {-1e30f, -1e30f, -1e30f}

__device__ __forceinline__ float ld_peer_f32(uint32_t local_saddr, uint32_t peer_rank) {
    uint32_t ra;
    float v;
    asm volatile("mapa.shared::cluster.u32 %0, %1, %2;"
                 : "=r"(ra) : "r"(local_saddr), "r"(peer_rank));
    asm volatile("ld.shared::cluster.f32 %0, [%1];" : "=f"(v) : "r"(ra));
    return v;
}

__global__ __launch_bounds__(NT, 6) __cluster_dims__(2, 1, 1)
void fine_matching_kernel(
    const float4* __restrict__ msm4,        // [P,R,S] as float4 (raw log-scores)
    const unsigned int* __restrict__ refm,  // [P,R] 32-bit bool
    const uint4* __restrict__ srcm4,        // [P,S] 32-bit bool as uint4
    const float* __restrict__ ncs,          // [P]
    float4* __restrict__ out4,              // [score | corr] as float4
    int write_corr)
{
    __shared__ __align__(16) float tile[64 * 132];   // half-tile, pitch 132
    __shared__ float cp1[128], cp2[128], cp3[128];   // my col partial top-3
    __shared__ __align__(16) float colT[128];        // merged col thresholds
    __shared__ float2 rowInfo[64];                   // (rowTx, refmaskF)

    const int bid  = blockIdx.x;
    const int p    = bid >> 1;
    const int half = bid & 1;                        // == cluster rank
    const uint32_t peer = (uint32_t)(half ^ 1);
    const int tid  = threadIdx.x;
    const int lane = tid & 31;

    // ---- P0/P1: masks; half-tile fill via cp.async (8 x 16B in flight)
    if (tid < 64)
        rowInfo[tid].y = (refm[p * 128 + half * 64 + tid] != 0u) ? 1.0f : 0.0f;

    {
        const float4* g = msm4 + p * 4096 + half * 2048 + tid;
        uint32_t sp = (uint32_t)__cvta_generic_to_shared(
            (float4*)tile + (tid >> 5) * 33 + lane);
        #pragma unroll
        for (int k = 0; k < 8; k++) {
            asm volatile("cp.async.cg.shared.global [%0], [%1], 16;"
                         :: "r"(sp + k * (8 * 33 * 16)), "l"(g + k * NT));
        }
        asm volatile("cp.async.commit_group;");
        asm volatile("cp.async.wait_group 0;" ::: "memory");
    }
    __syncthreads();

    // ---- P2: local scans (threads 0..127 cols, 128..255 rows)
    if (tid < 128) {
        // 1 thread per column, 64 rows, 4 interleaved accumulators
        const float* base = tile + tid;
        Top3 t0 = T3INIT, t1 = T3INIT, t2 = T3INIT, t3 = T3INIT;
        #pragma unroll
        for (int j = 0; j < 16; j++) {
            ins3(t0, base[(4 * j + 0) * 132]);
            ins3(t1, base[(4 * j + 1) * 132]);
            ins3(t2, base[(4 * j + 2) * 132]);
            ins3(t3, base[(4 * j + 3) * 132]);
        }
        merge(t0, t1);
        merge(t2, t3);
        merge(t0, t2);
        cp1[tid] = t0.v1;
        cp2[tid] = t0.v2;
        cp3[tid] = t0.v3;
    } else {
        // 2 threads per row (64 rows), LDS.128; half1 f4 20..31 then 16..19
        const int u  = tid - 128;
        const int r  = u >> 1;
        const int hf = u & 1;
        Top3 t0 = T3INIT, t1 = T3INIT, t2 = T3INIT, t3 = T3INIT;
        const float4* ra = (const float4*)tile + r * 33 + (hf ? 20 : 0);
        #pragma unroll
        for (int j = 0; j < 12; j++) {
            float4 v = ra[j];
            ins3(t0, v.x);
            ins3(t1, v.y);
            ins3(t2, v.z);
            ins3(t3, v.w);
        }
        const float4* rb = (const float4*)tile + r * 33 + (hf ? 16 : 12);
        #pragma unroll
        for (int j = 0; j < 4; j++) {
            float4 v = rb[j];
            ins3(t0, v.x);
            ins3(t1, v.y);
            ins3(t2, v.z);
            ins3(t3, v.w);
        }
        merge(t0, t1);
        merge(t2, t3);
        merge(t0, t2);
        merge_xor1(t0);
        if (!hf) rowInfo[r].x = t0.v3;
    }
    __syncthreads();

    // ---- Exchange col partials with cluster peer, merge
    asm volatile("barrier.cluster.arrive.aligned;" ::: "memory");
    asm volatile("barrier.cluster.wait.aligned;" ::: "memory");

    if (tid < 128) {
        Top3 t;
        t.v1 = cp1[tid];
        t.v2 = cp2[tid];
        t.v3 = cp3[tid];
        uint32_t a1 = (uint32_t)__cvta_generic_to_shared(cp1 + tid);
        uint32_t a2 = (uint32_t)__cvta_generic_to_shared(cp2 + tid);
        uint32_t a3 = (uint32_t)__cvta_generic_to_shared(cp3 + tid);
        ins3(t, ld_peer_f32(a1, peer));
        ins3(t, ld_peer_f32(a2, peer));
        ins3(t, ld_peer_f32(a3, peer));
        colT[tid] = t.v3;
    }
    __syncthreads();
    // done touching peer smem after this point; arrive now, wait at kernel end
    asm volatile("barrier.cluster.arrive.aligned;" ::: "memory");

    // ---- P3: dense output for my 64 rows; __stcs streaming stores
    const float scale = 0.5f * __ldg(ncs + p);
    const float4 cT = *(const float4*)(colT + 4 * lane);
    const uint4 smv = srcm4[p * 32 + lane];
    const float m0 = (smv.x != 0u) ? 1.f : 0.f;
    const float m1 = (smv.y != 0u) ? 1.f : 0.f;
    const float m2 = (smv.z != 0u) ? 1.f : 0.f;
    const float m3 = (smv.w != 0u) ? 1.f : 0.f;

    const float4* tp  = (const float4*)tile + (tid >> 5) * 33 + lane;
    const float2* rip = rowInfo + (tid >> 5);
    float4* sco = out4 + (size_t)p * 4096 + half * 2048 + tid;
    float4* cor = sco + (size_t)PP * 4096;

    if (write_corr) {
        #pragma unroll
        for (int k = 0; k < 8; k++) {
            float2 ri = rip[8 * k];             // warp-uniform (rowTx, refmaskF)
            float4 x  = tp[k * 8 * 33];

            bool ax = x.x >= ri.x, bx = x.x >= cT.x;
            bool ay = x.y >= ri.x, by = x.y >= cT.y;
            bool az = x.z >= ri.x, bz = x.z >= cT.z;
            bool aw = x.w >= ri.x, bw = x.w >= cT.w;

            float svx = scale * __expf(x.x), svy = scale * __expf(x.y);
            float svz = scale * __expf(x.z), svw = scale * __expf(x.w);

            float4 s4;
            s4.x = (ax ? svx : 0.f) + (bx ? svx : 0.f);
            s4.y = (ay ? svy : 0.f) + (by ? svy : 0.f);
            s4.z = (az ? svz : 0.f) + (bz ? svz : 0.f);
            s4.w = (aw ? svw : 0.f) + (bw ? svw : 0.f);
            __stcs(sco + k * NT, s4);

            float4 c4;
            c4.x = ((ax || bx) && x.x > XTHRESH) ? ri.y * m0 : 0.f;
            c4.y = ((ay || by) && x.y > XTHRESH) ? ri.y * m1 : 0.f;
            c4.z = ((az || bz) && x.z > XTHRESH) ? ri.y * m2 : 0.f;
            c4.w = ((aw || bw) && x.w > XTHRESH) ? ri.y * m3 : 0.f;
            __stcs(cor + k * NT, c4);
        }
    } else {
        #pragma unroll
        for (int k = 0; k < 8; k++) {
            float2 ri = rip[8 * k];
            float4 x  = tp[k * 8 * 33];
            bool ax = x.x >= ri.x, bx = x.x >= cT.x;
            bool ay = x.y >= ri.x, by = x.y >= cT.y;
            bool az = x.z >= ri.x, bz = x.z >= cT.z;
            bool aw = x.w >= ri.x, bw = x.w >= cT.w;
            float svx = scale * __expf(x.x), svy = scale * __expf(x.y);
            float svz = scale * __expf(x.z), svw = scale * __expf(x.w);
            float4 s4;
            s4.x = (ax ? svx : 0.f) + (bx ? svx : 0.f);
            s4.y = (ay ? svy : 0.f) + (by ? svy : 0.f);
            s4.z = (az ? svz : 0.f) + (bz ? svz : 0.f);
            s4.w = (aw ? svw : 0.f) + (bw ? svw : 0.f);
            __stcs(sco + k * NT, s4);
        }
    }

    // don't exit while peer may still read my cp arrays
    asm volatile("barrier.cluster.wait.aligned;" ::: "memory");
}

extern "C" void kernel_launch(void* const* d_in, const int* in_sizes, int n_in,
                              void* d_out, int out_size) {
    const float4* msm4       = (const float4*)d_in[0];
    const unsigned int* refm = (const unsigned int*)d_in[1];
    const uint4* srcm4       = (const uint4*)d_in[2];
    const float* ncs         = (const float*)d_in[3];
    float4* out4             = (float4*)d_out;

    const int prs = PP * 128 * 128;
    int write_corr = (out_size >= 2 * prs) ? 1 : 0;

    fine_matching_kernel<<<2 * PP, NT>>>(msm4, refm, srcm4, ncs, out4,
                                         write_corr);
}

// round 17
// speedup vs baseline: 1.1977x; 1.0428x over previous
#include <cuda_runtime.h>
#include <cuda_bf16.h>
#include <cstdint>

// FineMatching (P=512, R=S=128, K=3, THRESH=0.05, OR-combine, conditional).
// R17 = R9 + PUSH-based DSMEM exchange:
//   Column threads write their 3 partials into the PEER's cpP buffer via
//   mapa + st.shared::cluster right after the scan (producer-pays, off the
//   critical path). ONE cluster barrier (arrive=release / wait=acquire)
//   replaces R9's two barrier pairs + pre-exchange syncthreads; the merge
//   then reads LOCAL smem (29cyc) instead of 3x remote loads (215cyc), and
//   no trailing cluster wait is needed (no CTA touches peer smem after the
//   barrier). Everything else identical to R9 (best measured config).

#define PP 512
#define NT 256
#define XTHRESH (-2.99573227355f)   // ln(0.05)

struct Top3 { float v1, v2, v3; };

__device__ __forceinline__ void ins3(Top3& t, float v) {
    float t1 = fminf(t.v1, v);
    float t2 = fminf(t.v2, v);
    t.v1 = fmaxf(t.v1, v);
    t.v2 = fmaxf(t.v2, t1);
    t.v3 = fmaxf(t.v3, t2);
}

__device__ __forceinline__ void merge(Top3& a, const Top3& b) {
    ins3(a, b.v1);
    ins3(a, b.v2);
    ins3(a, b.v3);
}

__device__ __forceinline__ void merge_xor1(Top3& t) {
    Top3 b;
    b.v1 = __shfl_xor_sync(0xffffffffu, t.v1, 1);
    b.v2 = __shfl_xor_sync(0xffffffffu, t.v2, 1);
    b.v3 = __shfl_xor_sync(0xffffffffu, t.v3, 1);
    merge(t, b);
}

#define T3INIT {-1e30f, -1e30f, -1e30f}

// store one f32 into the peer CTA's smem at the same offset
__device__ __forceinline__ void st_peer_f32(uint32_t local_saddr,
                                            uint32_t peer_rank, float v) {
    uint32_t ra;
    asm volatile("mapa.shared::cluster.u32 %0, %1, %2;"
                 : "=r"(ra) : "r"(local_saddr), "r"(peer_rank));
    asm volatile("st.shared::cluster.f32 [%0], %1;"
                 :: "r"(ra), "f"(v) : "memory");
}

__global__ __launch_bounds__(NT, 6) __cluster_dims__(2, 1, 1)
void fine_matching_kernel(
    const float4* __restrict__ msm4,        // [P,R,S] as float4 (raw log-scores)
    const unsigned int* __restrict__ refm,  // [P,R] 32-bit bool
    const uint4* __restrict__ srcm4,        // [P,S] 32-bit bool as uint4
    const float* __restrict__ ncs,          // [P]
    float4* __restrict__ out4,              // [score | corr] as float4
    int write_corr)
{
    __shared__ __align__(16) float tile[64 * 132];   // half-tile, pitch 132
    __shared__ float cpP1[128], cpP2[128], cpP3[128]; // PEER-pushed col partials
    __shared__ __align__(16) float colT[128];        // merged col thresholds
    __shared__ float2 rowInfo[64];                   // (rowTx, refmaskF)

    const int bid  = blockIdx.x;
    const int p    = bid >> 1;
    const int half = bid & 1;                        // == cluster rank
    const uint32_t peer = (uint32_t)(half ^ 1);
    const int tid  = threadIdx.x;
    const int lane = tid & 31;

    // ---- P0/P1: masks; half-tile fill via cp.async (8 x 16B in flight)
    if (tid < 64)
        rowInfo[tid].y = (refm[p * 128 + half * 64 + tid] != 0u) ? 1.0f : 0.0f;

    {
        const float4* g = msm4 + p * 4096 + half * 2048 + tid;
        uint32_t sp = (uint32_t)__cvta_generic_to_shared(
            (float4*)tile + (tid >> 5) * 33 + lane);
        #pragma unroll
        for (int k = 0; k < 8; k++) {
            asm volatile("cp.async.cg.shared.global [%0], [%1], 16;"
                         :: "r"(sp + k * (8 * 33 * 16)), "l"(g + k * NT));
        }
        asm volatile("cp.async.commit_group;");
        asm volatile("cp.async.wait_group 0;" ::: "memory");
    }
    __syncthreads();

    // ---- P2: local scans; col threads PUSH partials to the peer's cpP
    Top3 t0 = T3INIT;
    if (tid < 128) {
        // 1 thread per column, 64 rows, 4 interleaved accumulators
        const float* base = tile + tid;
        Top3 t1 = T3INIT, t2 = T3INIT, t3 = T3INIT;
        #pragma unroll
        for (int j = 0; j < 16; j++) {
            ins3(t0, base[(4 * j + 0) * 132]);
            ins3(t1, base[(4 * j + 1) * 132]);
            ins3(t2, base[(4 * j + 2) * 132]);
            ins3(t3, base[(4 * j + 3) * 132]);
        }
        merge(t0, t1);
        merge(t2, t3);
        merge(t0, t2);
        // push my 3 partials into the PEER's cpP arrays (fire-and-forget)
        st_peer_f32((uint32_t)__cvta_generic_to_shared(cpP1 + tid), peer, t0.v1);
        st_peer_f32((uint32_t)__cvta_generic_to_shared(cpP2 + tid), peer, t0.v2);
        st_peer_f32((uint32_t)__cvta_generic_to_shared(cpP3 + tid), peer, t0.v3);
    } else {
        // 2 threads per row (64 rows), LDS.128; half1 f4 20..31 then 16..19
        const int u  = tid - 128;
        const int r  = u >> 1;
        const int hf = u & 1;
        Top3 s0 = T3INIT, s1 = T3INIT, s2 = T3INIT, s3 = T3INIT;
        const float4* ra = (const float4*)tile + r * 33 + (hf ? 20 : 0);
        #pragma unroll
        for (int j = 0; j < 12; j++) {
            float4 v = ra[j];
            ins3(s0, v.x);
            ins3(s1, v.y);
            ins3(s2, v.z);
            ins3(s3, v.w);
        }
        const float4* rb = (const float4*)tile + r * 33 + (hf ? 16 : 12);
        #pragma unroll
        for (int j = 0; j < 4; j++) {
            float4 v = rb[j];
            ins3(s0, v.x);
            ins3(s1, v.y);
            ins3(s2, v.z);
            ins3(s3, v.w);
        }
        merge(s0, s1);
        merge(s2, s3);
        merge(s0, s2);
        merge_xor1(s0);
        if (!hf) rowInfo[r].x = s0.v3;
    }

    // ---- ONE cluster barrier: release my pushes / acquire peer's pushes
    asm volatile("barrier.cluster.arrive.aligned;" ::: "memory");
    asm volatile("barrier.cluster.wait.aligned;" ::: "memory");
    // after this point no CTA touches peer smem -> no trailing barrier needed

    if (tid < 128) {
        // merge peer's pushed partials (LOCAL smem) into my register Top3
        ins3(t0, cpP1[tid]);
        ins3(t0, cpP2[tid]);
        ins3(t0, cpP3[tid]);
        colT[tid] = t0.v3;
    }
    __syncthreads();

    // ---- P3: dense output for my 64 rows; __stcs streaming stores
    const float scale = 0.5f * __ldg(ncs + p);
    const float4 cT = *(const float4*)(colT + 4 * lane);
    const uint4 smv = srcm4[p * 32 + lane];
    const float m0 = (smv.x != 0u) ? 1.f : 0.f;
    const float m1 = (smv.y != 0u) ? 1.f : 0.f;
    const float m2 = (smv.z != 0u) ? 1.f : 0.f;
    const float m3 = (smv.w != 0u) ? 1.f : 0.f;

    const float4* tp  = (const float4*)tile + (tid >> 5) * 33 + lane;
    const float2* rip = rowInfo + (tid >> 5);
    float4* sco = out4 + (size_t)p * 4096 + half * 2048 + tid;
    float4* cor = sco + (size_t)PP * 4096;

    if (write_corr) {
        #pragma unroll
        for (int k = 0; k < 8; k++) {
            float2 ri = rip[8 * k];             // warp-uniform (rowTx, refmaskF)
            float4 x  = tp[k * 8 * 33];

            bool ax = x.x >= ri.x, bx = x.x >= cT.x;
            bool ay = x.y >= ri.x, by = x.y >= cT.y;
            bool az = x.z >= ri.x, bz = x.z >= cT.z;
            bool aw = x.w >= ri.x, bw = x.w >= cT.w;

            float svx = scale * __expf(x.x), svy = scale * __expf(x.y);
            float svz = scale * __expf(x.z), svw = scale * __expf(x.w);

            float4 s4;
            s4.x = (ax ? svx : 0.f) + (bx ? svx : 0.f);
            s4.y = (ay ? svy : 0.f) + (by ? svy : 0.f);
            s4.z = (az ? svz : 0.f) + (bz ? svz : 0.f);
            s4.w = (aw ? svw : 0.f) + (bw ? svw : 0.f);
            __stcs(sco + k * NT, s4);

            float4 c4;
            c4.x = ((ax || bx) && x.x > XTHRESH) ? ri.y * m0 : 0.f;
            c4.y = ((ay || by) && x.y > XTHRESH) ? ri.y * m1 : 0.f;
            c4.z = ((az || bz) && x.z > XTHRESH) ? ri.y * m2 : 0.f;
            c4.w = ((aw || bw) && x.w > XTHRESH) ? ri.y * m3 : 0.f;
            __stcs(cor + k * NT, c4);
        }
    } else {
        #pragma unroll
        for (int k = 0; k < 8; k++) {
            float2 ri = rip[8 * k];
            float4 x  = tp[k * 8 * 33];
            bool ax = x.x >= ri.x, bx = x.x >= cT.x;
            bool ay = x.y >= ri.x, by = x.y >= cT.y;
            bool az = x.z >= ri.x, bz = x.z >= cT.z;
            bool aw = x.w >= ri.x, bw = x.w >= cT.w;
            float svx = scale * __expf(x.x), svy = scale * __expf(x.y);
            float svz = scale * __expf(x.z), svw = scale * __expf(x.w);
            float4 s4;
            s4.x = (ax ? svx : 0.f) + (bx ? svx : 0.f);
            s4.y = (ay ? svy : 0.f) + (by ? svy : 0.f);
            s4.z = (az ? svz : 0.f) + (bz ? svz : 0.f);
            s4.w = (aw ? svw : 0.f) + (bw ? svw : 0.f);
            __stcs(sco + k * NT, s4);
        }
    }
}

extern "C" void kernel_launch(void* const* d_in, const int* in_sizes, int n_in,
                              void* d_out, int out_size) {
    const float4* msm4       = (const float4*)d_in[0];
    const unsigned int* refm = (const unsigned int*)d_in[1];
    const uint4* srcm4       = (const uint4*)d_in[2];
    const float* ncs         = (const float*)d_in[3];
    float4* out4             = (float4*)d_out;

    const int prs = PP * 128 * 128;
    int write_corr = (out_size >= 2 * prs) ? 1 : 0;

    fine_matching_kernel<<<2 * PP, NT>>>(msm4, refm, srcm4, ncs, out4,
                                         write_corr);
}